// round 6
// baseline (speedup 1.0000x reference)
#include <cuda_runtime.h>
#include <math.h>

#define NPTS 1024
#define TLEN 64
#define CDIM 256
#define NTILE 16                         // 1024 / 64
#define NBLK (NTILE * (NTILE + 1) / 2)   // 136 triangular tiles

typedef unsigned long long ull;

// Scratch (__device__ globals — no allocation allowed).
__device__ float  g_xt[2][CDIM][NPTS];   // TRANSPOSED time-means: [w][k][m]
__device__ float  g_norm[2][NPTS];       // row squared norms
__device__ float  g_rs[2][NPTS];         // row sums of d (atomic-accumulated)
__device__ double g_acc[3];              // sum(dx*dy), sum(dx*dx), sum(dy*dy)
__device__ unsigned int g_ticket;        // last-block-done counter

// ---- packed f32x2 helpers (FFMA2 — ptxas won't emit from C++) ----
__device__ __forceinline__ void ffma2(ull& c, ull a, ull b) {
    asm("fma.rn.f32x2 %0, %1, %2, %0;" : "+l"(c) : "l"(a), "l"(b));
}
__device__ __forceinline__ ull dup2(float v) {
    ull r;
    asm("mov.b64 %0, {%1, %1};" : "=l"(r) : "f"(v));
    return r;
}
__device__ __forceinline__ float2 unpack2(ull v) {
    float2 r;
    asm("mov.b64 {%0, %1}, %2;" : "=f"(r.x), "=f"(r.y) : "l"(v));
    return r;
}

// ---------------------------------------------------------------------------
// Kernel 1: time-mean over T + per-row squared norm + TRANSPOSE to XT.
// grid (64, 2), block 256: each block owns 16 rows x all 256 channels.
// Thread: c4 = tid&63 (one float4 of channels), g = tid>>6: rows g,g+4,g+8,g+12.
// Means staged in shared, then written transposed (coalesced along m).
// ---------------------------------------------------------------------------
__global__ void __launch_bounds__(256) mean_t_kernel(const float* __restrict__ a,
                                                     const float* __restrict__ b) {
    const int w = blockIdx.y;
    const float* __restrict__ src = (w == 0) ? a : b;
    const int tid = threadIdx.x;
    const int c4  = tid & 63;
    const int g   = tid >> 6;
    const int n0  = blockIdx.x * 16;

    if (blockIdx.x == 0) {   // fold init
#pragma unroll
        for (int r = 0; r < 4; ++r) g_rs[w][tid + 256 * r] = 0.f;
        if (w == 0 && tid == 0) {
            g_acc[0] = 0.0; g_acc[1] = 0.0; g_acc[2] = 0.0;
            g_ticket = 0u;
        }
    }

    // 4 rows per thread, interleaved for MLP.
    const float4* __restrict__ p[4];
#pragma unroll
    for (int r = 0; r < 4; ++r)
        p[r] = (const float4*)(src + (size_t)(n0 + g + 4 * r) * (TLEN * CDIM)) + c4;

    float4 s[4];
#pragma unroll
    for (int r = 0; r < 4; ++r) s[r] = make_float4(0.f, 0.f, 0.f, 0.f);
#pragma unroll 4
    for (int t = 0; t < TLEN; ++t) {
#pragma unroll
        for (int r = 0; r < 4; ++r) {
            float4 v = __ldcs(p[r] + (size_t)t * (CDIM / 4));
            s[r].x += v.x; s[r].y += v.y; s[r].z += v.z; s[r].w += v.w;
        }
    }

    __shared__ float sm[16][261];   // means [row][c], pad 261 (conflict-free T reads)
    __shared__ float ssq[16][68];   // per-thread norm partials

    const float inv = 1.0f / TLEN;
#pragma unroll
    for (int r = 0; r < 4; ++r) {
        const int row = g + 4 * r;
        float4 m;
        m.x = s[r].x * inv; m.y = s[r].y * inv; m.z = s[r].z * inv; m.w = s[r].w * inv;
        sm[row][4 * c4 + 0] = m.x; sm[row][4 * c4 + 1] = m.y;
        sm[row][4 * c4 + 2] = m.z; sm[row][4 * c4 + 3] = m.w;
        ssq[row][c4] = m.x * m.x + m.y * m.y + m.z * m.z + m.w * m.w;
    }
    __syncthreads();

    // norms: 8 warps, 2 rows each
    {
        const int wr = tid >> 5, lane = tid & 31;
        const int row = 2 * wr + (lane >> 4), cc = lane & 15;
        float v = ssq[row][cc] + ssq[row][cc + 16] + ssq[row][cc + 32] + ssq[row][cc + 48];
#pragma unroll
        for (int off = 8; off > 0; off >>= 1)
            v += __shfl_down_sync(0xffffffffu, v, off, 16);
        if (cc == 0) g_norm[w][n0 + row] = v;
    }

    // transpose store: XT[c][n0 + nl], coalesced along nl
    const int nl = tid & 15;
#pragma unroll
    for (int q = 0; q < 16; ++q) {
        const int cc = (tid >> 4) + 16 * q;
        g_xt[w][cc][n0 + nl] = sm[nl][cc];
    }
}

// ---------------------------------------------------------------------------
// Kernel 2: triangular pairwise-distance GEMM, NO SHARED MEMORY operands.
// Reads XT directly: A = ulonglong2 (packed i-pairs), B = float4 along j —
// both contiguous per k, coalesced + L1/L2 cached. 64x64 tile, 256 threads,
// 4x4 micro-tile, f32x2 FMAs. Fused stats + ticket finalize. grid 136.
// ---------------------------------------------------------------------------
__global__ void __launch_bounds__(256) gemm_dist_fused_kernel(float* __restrict__ out) {
    const int t = blockIdx.x;
    int by = (int)((__fsqrt_rn(8.f * (float)t + 1.f) - 1.f) * 0.5f);
    while ((by + 1) * (by + 2) / 2 <= t) ++by;
    while (by * (by + 1) / 2 > t) --by;
    const int bx = t - by * (by + 1) / 2;
    const bool diag = (bx == by);
    const int I = bx * 64;   // rows
    const int J = by * 64;   // cols

    __shared__ float sh_rsx[64], sh_rsy[64];
    __shared__ float sh_csx[64], sh_csy[64];
    __shared__ float sh_p[3][8];
    __shared__ unsigned int s_last;

    const int tid = threadIdx.x;    // 0..255
    const int tx = tid & 15;        // j group (4 cols)
    const int ty = tid >> 4;        // i group (4 rows)

    if (tid < 64) { sh_csx[tid] = 0.f; sh_csy[tid] = 0.f; }

    ull accx[2][4], accy[2][4];     // [i-pair][j]
#pragma unroll
    for (int ip = 0; ip < 2; ++ip)
#pragma unroll
        for (int j = 0; j < 4; ++j) { accx[ip][j] = 0ull; accy[ip][j] = 0ull; }

    const float* __restrict__ XA = &g_xt[0][0][0];
    const float* __restrict__ XB = &g_xt[1][0][0];
    const int oA = I + 4 * ty;
    const int oB = J + 4 * tx;

#pragma unroll 8
    for (int k = 0; k < CDIM; ++k) {
        const float* rx = XA + (k << 10);
        ulonglong2 a2x = *(const ulonglong2*)(rx + oA);
        float4 b4x = *(const float4*)(rx + oB);
        const float* ry = XB + (k << 10);
        ulonglong2 a2y = *(const ulonglong2*)(ry + oA);
        float4 b4y = *(const float4*)(ry + oB);

        ull b0 = dup2(b4x.x), b1 = dup2(b4x.y), b2 = dup2(b4x.z), b3 = dup2(b4x.w);
        ffma2(accx[0][0], a2x.x, b0); ffma2(accx[0][1], a2x.x, b1);
        ffma2(accx[0][2], a2x.x, b2); ffma2(accx[0][3], a2x.x, b3);
        ffma2(accx[1][0], a2x.y, b0); ffma2(accx[1][1], a2x.y, b1);
        ffma2(accx[1][2], a2x.y, b2); ffma2(accx[1][3], a2x.y, b3);

        ull c0 = dup2(b4y.x), c1 = dup2(b4y.y), c2 = dup2(b4y.z), c3 = dup2(b4y.w);
        ffma2(accy[0][0], a2y.x, c0); ffma2(accy[0][1], a2y.x, c1);
        ffma2(accy[0][2], a2y.x, c2); ffma2(accy[0][3], a2y.x, c3);
        ffma2(accy[1][0], a2y.y, c0); ffma2(accy[1][1], a2y.y, c1);
        ffma2(accy[1][2], a2y.y, c2); ffma2(accy[1][3], a2y.y, c3);
    }

    // -------- Epilogue: distances in registers, fused statistics --------
    float nIx[4], nIy[4], nJx[4], nJy[4];
#pragma unroll
    for (int i = 0; i < 4; ++i) {
        nIx[i] = g_norm[0][I + ty * 4 + i];
        nIy[i] = g_norm[1][I + ty * 4 + i];
    }
#pragma unroll
    for (int j = 0; j < 4; ++j) {
        nJx[j] = g_norm[0][J + tx * 4 + j];
        nJy[j] = g_norm[1][J + tx * 4 + j];
    }

    float pxy = 0.f, pxx = 0.f, pyy = 0.f;
    float rowx[4], rowy[4], colx[4] = {0, 0, 0, 0}, coly[4] = {0, 0, 0, 0};

#pragma unroll
    for (int ip = 0; ip < 2; ++ip) {
        float2 cx[4], cy[4];
#pragma unroll
        for (int j = 0; j < 4; ++j) { cx[j] = unpack2(accx[ip][j]); cy[j] = unpack2(accy[ip][j]); }
#pragma unroll
        for (int h = 0; h < 2; ++h) {
            const int i = 2 * ip + h;
            float rx = 0.f, ry = 0.f;
#pragma unroll
            for (int j = 0; j < 4; ++j) {
                const float gx = h ? cx[j].y : cx[j].x;
                const float gy = h ? cy[j].y : cy[j].x;
                const float dx = sqrtf(fmaxf(nIx[i] + nJx[j] - 2.f * gx, 0.f) + 1e-12f);
                const float dy = sqrtf(fmaxf(nIy[i] + nJy[j] - 2.f * gy, 0.f) + 1e-12f);
                pxy = fmaf(dx, dy, pxy);
                pxx = fmaf(dx, dx, pxx);
                pyy = fmaf(dy, dy, pyy);
                rx += dx; ry += dy;
                colx[j] += dx; coly[j] += dy;
            }
            rowx[i] = rx; rowy[i] = ry;
        }
    }

    // row sums across tx (16-lane subgroups share ty)
#pragma unroll
    for (int i = 0; i < 4; ++i) {
        float rx = rowx[i], ry = rowy[i];
#pragma unroll
        for (int off = 8; off > 0; off >>= 1) {
            rx += __shfl_down_sync(0xffffffffu, rx, off, 16);
            ry += __shfl_down_sync(0xffffffffu, ry, off, 16);
        }
        if (tx == 0) { sh_rsx[ty * 4 + i] = rx; sh_rsy[ty * 4 + i] = ry; }
    }
    __syncthreads();
#pragma unroll
    for (int j = 0; j < 4; ++j) {
        atomicAdd(&sh_csx[tx * 4 + j], colx[j]);
        atomicAdd(&sh_csy[tx * 4 + j], coly[j]);
    }

#pragma unroll
    for (int off = 16; off > 0; off >>= 1) {
        pxy += __shfl_down_sync(0xffffffffu, pxy, off);
        pxx += __shfl_down_sync(0xffffffffu, pxx, off);
        pyy += __shfl_down_sync(0xffffffffu, pyy, off);
    }
    if ((tid & 31) == 0) {
        sh_p[0][tid >> 5] = pxy; sh_p[1][tid >> 5] = pxx; sh_p[2][tid >> 5] = pyy;
    }
    __syncthreads();

    if (tid < 64) {
        atomicAdd(&g_rs[0][I + tid], sh_rsx[tid]);
        atomicAdd(&g_rs[1][I + tid], sh_rsy[tid]);
        if (!diag) {
            atomicAdd(&g_rs[0][J + tid], sh_csx[tid]);
            atomicAdd(&g_rs[1][J + tid], sh_csy[tid]);
        }
    }
    if (tid == 0) {
        const double scl = diag ? 1.0 : 2.0;
        double s0 = 0, s1 = 0, s2 = 0;
#pragma unroll
        for (int q = 0; q < 8; ++q) { s0 += sh_p[0][q]; s1 += sh_p[1][q]; s2 += sh_p[2][q]; }
        atomicAdd(&g_acc[0], scl * s0);
        atomicAdd(&g_acc[1], scl * s1);
        atomicAdd(&g_acc[2], scl * s2);
    }

    // -------- last-block finalize (threadfence + ticket) --------
    __threadfence();
    __syncthreads();
    if (tid == 0) s_last = (atomicAdd(&g_ticket, 1u) == NBLK - 1) ? 1u : 0u;
    __syncthreads();
    if (s_last == 0u) return;
    __threadfence();

    // sum(a*b) = S_xy - (2/N) * sum_i Rx_i*Ry_i + Tx*Ty/N^2 (double precision)
    double sRR = 0.0, sXX = 0.0, sYY = 0.0, sX = 0.0, sY = 0.0;
#pragma unroll
    for (int q = 0; q < 4; ++q) {
        const int i = tid + q * 256;
        const double rx = (double)g_rs[0][i];
        const double ry = (double)g_rs[1][i];
        sRR += rx * ry; sXX += rx * rx; sYY += ry * ry; sX += rx; sY += ry;
    }
#pragma unroll
    for (int off = 16; off > 0; off >>= 1) {
        sRR += __shfl_down_sync(0xffffffffu, sRR, off);
        sXX += __shfl_down_sync(0xffffffffu, sXX, off);
        sYY += __shfl_down_sync(0xffffffffu, sYY, off);
        sX  += __shfl_down_sync(0xffffffffu, sX, off);
        sY  += __shfl_down_sync(0xffffffffu, sY, off);
    }
    __shared__ double sd[5][8];
    const int lane = tid & 31, wid = tid >> 5;
    if (lane == 0) { sd[0][wid] = sRR; sd[1][wid] = sXX; sd[2][wid] = sYY; sd[3][wid] = sX; sd[4][wid] = sY; }
    __syncthreads();
    if (tid == 0) {
        double a0 = 0, a1 = 0, a2 = 0, a3 = 0, a4 = 0;
#pragma unroll
        for (int q = 0; q < 8; ++q) {
            a0 += sd[0][q]; a1 += sd[1][q]; a2 += sd[2][q]; a3 += sd[3][q]; a4 += sd[4][q];
        }
        const double N = (double)NPTS, N2 = N * N;
        const double sumab = g_acc[0] - (2.0 / N) * a0 + (a3 * a4) / N2;
        const double sumaa = g_acc[1] - (2.0 / N) * a1 + (a3 * a3) / N2;
        const double sumbb = g_acc[2] - (2.0 / N) * a2 + (a4 * a4) / N2;
        const double mxy = sumab / N2, mxx = sumaa / N2, myy = sumbb / N2;
        const double r = mxy / sqrt(mxx * myy + 1e-9);
        out[0] = (float)(1.0 - r);
    }
}

extern "C" void kernel_launch(void* const* d_in, const int* in_sizes, int n_in,
                              void* d_out, int out_size) {
    const float* a = (const float*)d_in[0];  // output_1 (1024,64,256) f32
    const float* b = (const float*)d_in[1];  // feature  (1024,64,256) f32
    // d_in[2] = mask, unused by the reference module.

    mean_t_kernel<<<dim3(NPTS / 16, 2), 256>>>(a, b);
    gemm_dist_fused_kernel<<<NBLK, 256>>>((float*)d_out);
}

// round 7
// speedup vs baseline: 2.1659x; 2.1659x over previous
#include <cuda_runtime.h>
#include <math.h>

#define NPTS 1024
#define TLEN 64
#define CDIM 256
#define NTILE 16                         // 1024 / 64
#define NBLK (NTILE * (NTILE + 1) / 2)   // 136 triangular tiles

// Scratch (__device__ globals — no allocation allowed).
__device__ float  g_xm[2][NPTS * CDIM];  // time-means (x, y), row-major
__device__ float  g_norm[2][NPTS];       // row squared norms
__device__ float  g_rs[2][NPTS];         // row sums of d (atomic-accumulated)
__device__ double g_acc[3];              // sum(dx*dy), sum(dx*dx), sum(dy*dy)
__device__ unsigned int g_ticket;        // last-block-done counter

__device__ __forceinline__ unsigned int f2tf(float v) {
    unsigned int r;
    asm("cvt.rna.tf32.f32 %0, %1;" : "=r"(r) : "f"(v));
    return r;
}
__device__ __forceinline__ void mma_tf32(float* c,
                                         unsigned int a0, unsigned int a1,
                                         unsigned int a2, unsigned int a3,
                                         unsigned int b0, unsigned int b1) {
    asm("mma.sync.aligned.m16n8k8.row.col.f32.tf32.tf32.f32 "
        "{%0,%1,%2,%3},{%4,%5,%6,%7},{%8,%9},{%0,%1,%2,%3};"
        : "+f"(c[0]), "+f"(c[1]), "+f"(c[2]), "+f"(c[3])
        : "r"(a0), "r"(a1), "r"(a2), "r"(a3), "r"(b0), "r"(b1));
}

// ---------------------------------------------------------------------------
// Kernel 1: time-mean over T + per-row squared norm (HBM-ceiling bound).
// grid (512, 2), block 256: 2 rows/block, 128 threads/row.
// ---------------------------------------------------------------------------
__global__ void mean_norm_kernel(const float* __restrict__ a,
                                 const float* __restrict__ b) {
    const int w = blockIdx.y;
    const float* __restrict__ src = (w == 0) ? a : b;
    const int tid  = threadIdx.x;
    const int row  = tid >> 7;
    const int half = (tid >> 6) & 1;
    const int c4   = tid & 63;
    const int n    = blockIdx.x * 2 + row;

    if (blockIdx.x == 0) {   // fold init
#pragma unroll
        for (int r = 0; r < 4; ++r) g_rs[w][tid + 256 * r] = 0.f;
        if (w == 0 && tid == 0) {
            g_acc[0] = 0.0; g_acc[1] = 0.0; g_acc[2] = 0.0;
            g_ticket = 0u;
        }
    }

    const float4* __restrict__ p =
        (const float4*)(src + (size_t)n * (TLEN * CDIM)) + half * 32 * (CDIM / 4) + c4;
    float4 s0 = make_float4(0.f, 0.f, 0.f, 0.f);
    float4 s1 = make_float4(0.f, 0.f, 0.f, 0.f);
#pragma unroll
    for (int t = 0; t < 16; ++t) {
        float4 v0 = __ldcs(p + (size_t)(2 * t) * (CDIM / 4));
        float4 v1 = __ldcs(p + (size_t)(2 * t + 1) * (CDIM / 4));
        s0.x += v0.x; s0.y += v0.y; s0.z += v0.z; s0.w += v0.w;
        s1.x += v1.x; s1.y += v1.y; s1.z += v1.z; s1.w += v1.w;
    }
    float4 s;
    s.x = s0.x + s1.x; s.y = s0.y + s1.y; s.z = s0.z + s1.z; s.w = s0.w + s1.w;

    __shared__ float4 sh[2][2][64];
    __shared__ float part[2][2];
    sh[row][half][c4] = s;
    __syncthreads();

    if (half == 0) {
        const float4 o = sh[row][1][c4];
        const float inv = 1.0f / TLEN;
        float4 m;
        m.x = (s.x + o.x) * inv; m.y = (s.y + o.y) * inv;
        m.z = (s.z + o.z) * inv; m.w = (s.w + o.w) * inv;
        ((float4*)(g_xm[w] + (size_t)n * CDIM))[c4] = m;

        float sq = m.x * m.x + m.y * m.y + m.z * m.z + m.w * m.w;
#pragma unroll
        for (int off = 16; off > 0; off >>= 1)
            sq += __shfl_down_sync(0xffffffffu, sq, off);
        if ((c4 & 31) == 0) part[row][c4 >> 5] = sq;
    }
    __syncthreads();
    if ((tid & 127) == 0) g_norm[w][n] = part[row][0] + part[row][1];
}

// ---------------------------------------------------------------------------
// Kernel 2: triangular pairwise-distance GEMM on TENSOR CORES (tf32 mma.sync)
// with fused statistics and ticket finalize. 64x64 tile, 256 threads (8 warps
// in 4x2: warp tile 16 rows x 32 cols). K-chunks of 32 staged in smem as
// pre-converted tf32 bits. d never materialized; diagonal overridden to 1e-6.
// ---------------------------------------------------------------------------
__global__ void __launch_bounds__(256) gemm_mma_kernel(float* __restrict__ out) {
    const int tb = blockIdx.x;
    int by = (int)((__fsqrt_rn(8.f * (float)tb + 1.f) - 1.f) * 0.5f);
    while ((by + 1) * (by + 2) / 2 <= tb) ++by;
    while (by * (by + 1) / 2 > tb) --by;
    const int bx = tb - by * (by + 1) / 2;
    const bool diag = (bx == by);
    const int I = bx * 64;   // rows
    const int J = by * 64;   // cols

    __shared__ unsigned int sA[2][64][36];   // [w][m][k] tf32 bits (I-rows)
    __shared__ unsigned int sB[2][64][36];   // [w][n][k] tf32 bits (J-rows)
    __shared__ float sh_rs[2][64], sh_cs[2][64];
    __shared__ float sh_p[3][8];
    __shared__ unsigned int s_last;

    const int tid  = threadIdx.x;
    const int warp = tid >> 5, lane = tid & 31;
    const int wr = warp >> 1, wc = warp & 1;   // 4x2 warp grid
    const int g = lane >> 2, tig = lane & 3;

    if (tid < 128) {
        const int w2 = tid >> 6;
        sh_rs[w2][tid & 63] = 0.f;
        sh_cs[w2][tid & 63] = 0.f;
    }

    float cx[4][4], cy[4][4];
#pragma unroll
    for (int t = 0; t < 4; ++t)
#pragma unroll
        for (int q = 0; q < 4; ++q) { cx[t][q] = 0.f; cy[t][q] = 0.f; }

    // fill mapping: m = tid>>2 (0..63), kq = (tid&3)*8 : 8 floats (2 float4)
    const int m  = tid >> 2;
    const int kq = (tid & 3) * 8;

    float4 fA[2][2], fB[2][2];
#pragma unroll
    for (int w = 0; w < 2; ++w)
#pragma unroll
        for (int q = 0; q < 2; ++q) {
            fA[w][q] = *(const float4*)(g_xm[w] + (size_t)(I + m) * CDIM + kq + 4 * q);
            fB[w][q] = *(const float4*)(g_xm[w] + (size_t)(J + m) * CDIM + kq + 4 * q);
        }

    for (int c = 0; c < 8; ++c) {
        __syncthreads();
#pragma unroll
        for (int w = 0; w < 2; ++w)
#pragma unroll
            for (int q = 0; q < 2; ++q) {
                uint4 ua, ub;
                ua.x = f2tf(fA[w][q].x); ua.y = f2tf(fA[w][q].y);
                ua.z = f2tf(fA[w][q].z); ua.w = f2tf(fA[w][q].w);
                *(uint4*)&sA[w][m][kq + 4 * q] = ua;
                ub.x = f2tf(fB[w][q].x); ub.y = f2tf(fB[w][q].y);
                ub.z = f2tf(fB[w][q].z); ub.w = f2tf(fB[w][q].w);
                *(uint4*)&sB[w][m][kq + 4 * q] = ub;
            }
        __syncthreads();
        if (c < 7) {
            const int k0 = (c + 1) * 32;
#pragma unroll
            for (int w = 0; w < 2; ++w)
#pragma unroll
                for (int q = 0; q < 2; ++q) {
                    fA[w][q] = *(const float4*)(g_xm[w] + (size_t)(I + m) * CDIM + k0 + kq + 4 * q);
                    fB[w][q] = *(const float4*)(g_xm[w] + (size_t)(J + m) * CDIM + k0 + kq + 4 * q);
                }
        }
#pragma unroll
        for (int kk = 0; kk < 4; ++kk) {
            const int kb = kk * 8;
            const int r0 = 16 * wr + g, r1 = r0 + 8;
            const unsigned int ax0 = sA[0][r0][kb + tig];
            const unsigned int ax1 = sA[0][r1][kb + tig];
            const unsigned int ax2 = sA[0][r0][kb + tig + 4];
            const unsigned int ax3 = sA[0][r1][kb + tig + 4];
            const unsigned int ay0 = sA[1][r0][kb + tig];
            const unsigned int ay1 = sA[1][r1][kb + tig];
            const unsigned int ay2 = sA[1][r0][kb + tig + 4];
            const unsigned int ay3 = sA[1][r1][kb + tig + 4];
#pragma unroll
            for (int t = 0; t < 4; ++t) {
                const int nr = 32 * wc + 8 * t + g;
                const unsigned int bx0 = sB[0][nr][kb + tig];
                const unsigned int bx1 = sB[0][nr][kb + tig + 4];
                mma_tf32(cx[t], ax0, ax1, ax2, ax3, bx0, bx1);
                const unsigned int by0 = sB[1][nr][kb + tig];
                const unsigned int by1 = sB[1][nr][kb + tig + 4];
                mma_tf32(cy[t], ay0, ay1, ay2, ay3, by0, by1);
            }
        }
    }

    // -------- Epilogue: distances from gram, fused statistics --------
    const int gr0 = I + 16 * wr + g, gr1 = gr0 + 8;
    const float nIx0 = g_norm[0][gr0], nIx1 = g_norm[0][gr1];
    const float nIy0 = g_norm[1][gr0], nIy1 = g_norm[1][gr1];

    float pxy = 0.f, pxx = 0.f, pyy = 0.f;
    float prx0 = 0.f, prx1 = 0.f, pry0 = 0.f, pry1 = 0.f;

#pragma unroll
    for (int t = 0; t < 4; ++t) {
        const int colL = 32 * wc + 8 * t + 2 * tig;    // local col
        const int gcA = J + colL, gcB = gcA + 1;
        const float nJxA = g_norm[0][gcA], nJxB = g_norm[0][gcB];
        const float nJyA = g_norm[1][gcA], nJyB = g_norm[1][gcB];

        float dx00 = sqrtf(fmaxf(nIx0 + nJxA - 2.f * cx[t][0], 0.f) + 1e-12f);
        float dx01 = sqrtf(fmaxf(nIx0 + nJxB - 2.f * cx[t][1], 0.f) + 1e-12f);
        float dx10 = sqrtf(fmaxf(nIx1 + nJxA - 2.f * cx[t][2], 0.f) + 1e-12f);
        float dx11 = sqrtf(fmaxf(nIx1 + nJxB - 2.f * cx[t][3], 0.f) + 1e-12f);
        float dy00 = sqrtf(fmaxf(nIy0 + nJyA - 2.f * cy[t][0], 0.f) + 1e-12f);
        float dy01 = sqrtf(fmaxf(nIy0 + nJyB - 2.f * cy[t][1], 0.f) + 1e-12f);
        float dy10 = sqrtf(fmaxf(nIy1 + nJyA - 2.f * cy[t][2], 0.f) + 1e-12f);
        float dy11 = sqrtf(fmaxf(nIy1 + nJyB - 2.f * cy[t][3], 0.f) + 1e-12f);

        if (gr0 == gcA) { dx00 = 1e-6f; dy00 = 1e-6f; }   // exact diagonal
        if (gr0 == gcB) { dx01 = 1e-6f; dy01 = 1e-6f; }
        if (gr1 == gcA) { dx10 = 1e-6f; dy10 = 1e-6f; }
        if (gr1 == gcB) { dx11 = 1e-6f; dy11 = 1e-6f; }

        pxy += dx00 * dy00 + dx01 * dy01 + dx10 * dy10 + dx11 * dy11;
        pxx += dx00 * dx00 + dx01 * dx01 + dx10 * dx10 + dx11 * dx11;
        pyy += dy00 * dy00 + dy01 * dy01 + dy10 * dy10 + dy11 * dy11;

        prx0 += dx00 + dx01; prx1 += dx10 + dx11;
        pry0 += dy00 + dy01; pry1 += dy10 + dy11;

        // column sums: combine this thread's two rows, reduce over g (8 lanes)
        float vxA = dx00 + dx10, vxB = dx01 + dx11;
        float vyA = dy00 + dy10, vyB = dy01 + dy11;
#pragma unroll
        for (int s = 16; s >= 4; s >>= 1) {
            vxA += __shfl_down_sync(0xffffffffu, vxA, s);
            vxB += __shfl_down_sync(0xffffffffu, vxB, s);
            vyA += __shfl_down_sync(0xffffffffu, vyA, s);
            vyB += __shfl_down_sync(0xffffffffu, vyB, s);
        }
        if (g == 0) {
            atomicAdd(&sh_cs[0][colL],     vxA);
            atomicAdd(&sh_cs[0][colL + 1], vxB);
            atomicAdd(&sh_cs[1][colL],     vyA);
            atomicAdd(&sh_cs[1][colL + 1], vyB);
        }
    }

    // row sums: reduce over tig (quad)
    prx0 += __shfl_down_sync(0xffffffffu, prx0, 2, 4);
    prx0 += __shfl_down_sync(0xffffffffu, prx0, 1, 4);
    prx1 += __shfl_down_sync(0xffffffffu, prx1, 2, 4);
    prx1 += __shfl_down_sync(0xffffffffu, prx1, 1, 4);
    pry0 += __shfl_down_sync(0xffffffffu, pry0, 2, 4);
    pry0 += __shfl_down_sync(0xffffffffu, pry0, 1, 4);
    pry1 += __shfl_down_sync(0xffffffffu, pry1, 2, 4);
    pry1 += __shfl_down_sync(0xffffffffu, pry1, 1, 4);
    if (tig == 0) {
        atomicAdd(&sh_rs[0][16 * wr + g],     prx0);
        atomicAdd(&sh_rs[0][16 * wr + g + 8], prx1);
        atomicAdd(&sh_rs[1][16 * wr + g],     pry0);
        atomicAdd(&sh_rs[1][16 * wr + g + 8], pry1);
    }

    // scalar products: warp reduce -> shared
#pragma unroll
    for (int off = 16; off > 0; off >>= 1) {
        pxy += __shfl_down_sync(0xffffffffu, pxy, off);
        pxx += __shfl_down_sync(0xffffffffu, pxx, off);
        pyy += __shfl_down_sync(0xffffffffu, pyy, off);
    }
    if (lane == 0) { sh_p[0][warp] = pxy; sh_p[1][warp] = pxx; sh_p[2][warp] = pyy; }
    __syncthreads();

    if (tid < 64) {
        atomicAdd(&g_rs[0][I + tid], sh_rs[0][tid]);
        atomicAdd(&g_rs[1][I + tid], sh_rs[1][tid]);
        if (!diag) {
            atomicAdd(&g_rs[0][J + tid], sh_cs[0][tid]);
            atomicAdd(&g_rs[1][J + tid], sh_cs[1][tid]);
        }
    }
    if (tid == 0) {
        const double scl = diag ? 1.0 : 2.0;
        double s0 = 0, s1 = 0, s2 = 0;
#pragma unroll
        for (int q = 0; q < 8; ++q) { s0 += sh_p[0][q]; s1 += sh_p[1][q]; s2 += sh_p[2][q]; }
        atomicAdd(&g_acc[0], scl * s0);
        atomicAdd(&g_acc[1], scl * s1);
        atomicAdd(&g_acc[2], scl * s2);
    }

    // -------- last-block finalize (threadfence + ticket) --------
    __threadfence();
    __syncthreads();
    if (tid == 0) s_last = (atomicAdd(&g_ticket, 1u) == NBLK - 1) ? 1u : 0u;
    __syncthreads();
    if (s_last == 0u) return;
    __threadfence();

    double sRR = 0.0, sXX = 0.0, sYY = 0.0, sX = 0.0, sY = 0.0;
#pragma unroll
    for (int q = 0; q < 4; ++q) {
        const int i = tid + q * 256;
        const double rx = (double)g_rs[0][i];
        const double ry = (double)g_rs[1][i];
        sRR += rx * ry; sXX += rx * rx; sYY += ry * ry; sX += rx; sY += ry;
    }
#pragma unroll
    for (int off = 16; off > 0; off >>= 1) {
        sRR += __shfl_down_sync(0xffffffffu, sRR, off);
        sXX += __shfl_down_sync(0xffffffffu, sXX, off);
        sYY += __shfl_down_sync(0xffffffffu, sYY, off);
        sX  += __shfl_down_sync(0xffffffffu, sX, off);
        sY  += __shfl_down_sync(0xffffffffu, sY, off);
    }
    __shared__ double sd[5][8];
    if (lane == 0) { sd[0][warp] = sRR; sd[1][warp] = sXX; sd[2][warp] = sYY; sd[3][warp] = sX; sd[4][warp] = sY; }
    __syncthreads();
    if (tid == 0) {
        double a0 = 0, a1 = 0, a2 = 0, a3 = 0, a4 = 0;
#pragma unroll
        for (int q = 0; q < 8; ++q) {
            a0 += sd[0][q]; a1 += sd[1][q]; a2 += sd[2][q]; a3 += sd[3][q]; a4 += sd[4][q];
        }
        const double N = (double)NPTS, N2 = N * N;
        const double sumab = g_acc[0] - (2.0 / N) * a0 + (a3 * a4) / N2;
        const double sumaa = g_acc[1] - (2.0 / N) * a1 + (a3 * a3) / N2;
        const double sumbb = g_acc[2] - (2.0 / N) * a2 + (a4 * a4) / N2;
        const double mxy = sumab / N2, mxx = sumaa / N2, myy = sumbb / N2;
        const double r = mxy / sqrt(mxx * myy + 1e-9);
        out[0] = (float)(1.0 - r);
    }
}

extern "C" void kernel_launch(void* const* d_in, const int* in_sizes, int n_in,
                              void* d_out, int out_size) {
    const float* a = (const float*)d_in[0];  // output_1 (1024,64,256) f32
    const float* b = (const float*)d_in[1];  // feature  (1024,64,256) f32
    // d_in[2] = mask, unused by the reference module.

    mean_norm_kernel<<<dim3(NPTS / 2, 2), 256>>>(a, b);
    gemm_mma_kernel<<<NBLK, 256>>>((float*)d_out);
}